// round 13
// baseline (speedup 1.0000x reference)
#include <cuda_runtime.h>
#include <cstdint>
#include <cstddef>

#define NC    4
#define CC    64
#define DC    192
#define TPAD  196
#define GPAD  68
#define QQ    512
#define ND    (NC*DC)
#define IDIM  768
#define EPSF  1e-8f
#define SQ194 194

__device__ float g_hatm[NC*CC*DC];
__device__ float g_hq[QQ*ND];
__device__ float g_G[NC*CC*CC];
__device__ float g_mu[NC*CC];
__device__ float g_sxx[NC*CC];
__device__ float g_dq0[QQ*NC*CC];
__device__ float g_S1[QQ*NC];
__device__ float g_ss[QQ*NC];

typedef unsigned long long u64;
__device__ __forceinline__ void f2unpack(u64 v, float& lo, float& hi) {
    asm("mov.b64 {%0, %1}, %2;" : "=f"(lo), "=f"(hi) : "l"(v));
}
__device__ __forceinline__ u64 f2dup(float a) {
    u64 r;
    asm("mov.b64 %0, {%1, %1};" : "=l"(r) : "f"(a));
    return r;
}
__device__ __forceinline__ u64 ffma2(u64 a, u64 b, u64 c) {
    u64 d;
    asm("fma.rn.f32x2 %0, %1, %2, %3;" : "=l"(d) : "l"(a), "l"(b), "l"(c));
    return d;
}

// =============================================================================
// Kernel A: fused GEMM  C[576 x 768] = [m;q] @ Wl^T  (FFMA2, double-buffered)
// =============================================================================
#define GBM 48
#define GBN 64
#define GKT 64
#define APAD 68
#define ABUF (GBM*APAD)
#define BBUF (GKT*(GBN+4))
#define TILEBUF (ABUF + BBUF)

__global__ __launch_bounds__(256, 1)
void gemm_kernel(const float* __restrict__ Am, const float* __restrict__ Aq,
                 const float* __restrict__ W,  const float* __restrict__ Bb)
{
    extern __shared__ __align__(16) float smG[];

    const int t   = threadIdx.x;
    const int tx  = t & 15;
    const int ty  = t >> 4;
    const int row0 = blockIdx.y * GBM;
    const int col0 = blockIdx.x * GBN;

    const float* aptr[3];
    int arow[3], acol[3];
#pragma unroll
    for (int j = 0; j < 3; j++) {
        const int i = t + 256 * j;
        arow[j] = i >> 4;
        acol[j] = (i & 15) << 2;
        const int rg = row0 + arow[j];
        aptr[j] = ((rg < 64) ? (Am + (size_t)rg * IDIM)
                             : (Aq + (size_t)(rg - 64) * IDIM)) + acol[j];
    }

    const int lb_j = t >> 2;
    const int lb_k = (t & 3) << 2;
    const int gj = col0 + lb_j;
    const int bn = gj / DC;
    const int bd = gj - bn * DC;
    const float* brow = W + ((size_t)bn * CC * DC + bd) * IDIM + lb_k;

    {
        float* As = smG;
        float* Bs = smG + ABUF;
#pragma unroll
        for (int j = 0; j < 3; j++) {
            float4 a = *(const float4*)(aptr[j]);
            *(float4*)&As[arow[j] * APAD + acol[j]] = a;
        }
#pragma unroll
        for (int c = 0; c < 4; c++) {
            float4 b = *(const float4*)(brow + 16 * c);
            Bs[(lb_k + 16 * c + 0) * (GBN + 4) + lb_j] = b.x;
            Bs[(lb_k + 16 * c + 1) * (GBN + 4) + lb_j] = b.y;
            Bs[(lb_k + 16 * c + 2) * (GBN + 4) + lb_j] = b.z;
            Bs[(lb_k + 16 * c + 3) * (GBN + 4) + lb_j] = b.w;
        }
    }
    __syncthreads();

    u64 acc[3][2];
#pragma unroll
    for (int i = 0; i < 3; i++) { acc[i][0] = 0ull; acc[i][1] = 0ull; }

#pragma unroll 1
    for (int it = 0; it < IDIM / GKT; it++) {
        const float* Asc = smG + (it & 1) * TILEBUF;
        const float* Bsc = Asc + ABUF;

        float4 ar0, ar1, ar2, br0, br1, br2, br3;
        const bool pf = (it < IDIM / GKT - 1);
        if (pf) {
            const int kt = (it + 1) * GKT;
            ar0 = *(const float4*)(aptr[0] + kt);
            ar1 = *(const float4*)(aptr[1] + kt);
            ar2 = *(const float4*)(aptr[2] + kt);
            br0 = *(const float4*)(brow + kt);
            br1 = *(const float4*)(brow + kt + 16);
            br2 = *(const float4*)(brow + kt + 32);
            br3 = *(const float4*)(brow + kt + 48);
        }

#pragma unroll 16
        for (int k = 0; k < GKT; k++) {
            ulonglong2 bp = *(const ulonglong2*)&Bsc[k * (GBN + 4) + (tx << 2)];
            u64 a0 = f2dup(Asc[(ty * 3 + 0) * APAD + k]);
            u64 a1 = f2dup(Asc[(ty * 3 + 1) * APAD + k]);
            u64 a2 = f2dup(Asc[(ty * 3 + 2) * APAD + k]);
            acc[0][0] = ffma2(a0, bp.x, acc[0][0]);
            acc[0][1] = ffma2(a0, bp.y, acc[0][1]);
            acc[1][0] = ffma2(a1, bp.x, acc[1][0]);
            acc[1][1] = ffma2(a1, bp.y, acc[1][1]);
            acc[2][0] = ffma2(a2, bp.x, acc[2][0]);
            acc[2][1] = ffma2(a2, bp.y, acc[2][1]);
        }
        __syncthreads();

        if (pf) {
            float* Asn = smG + ((it + 1) & 1) * TILEBUF;
            float* Bsn = Asn + ABUF;
            *(float4*)&Asn[arow[0] * APAD + acol[0]] = ar0;
            *(float4*)&Asn[arow[1] * APAD + acol[1]] = ar1;
            *(float4*)&Asn[arow[2] * APAD + acol[2]] = ar2;
            Bsn[(lb_k + 0) * (GBN + 4) + lb_j]  = br0.x;
            Bsn[(lb_k + 1) * (GBN + 4) + lb_j]  = br0.y;
            Bsn[(lb_k + 2) * (GBN + 4) + lb_j]  = br0.z;
            Bsn[(lb_k + 3) * (GBN + 4) + lb_j]  = br0.w;
            Bsn[(lb_k + 16) * (GBN + 4) + lb_j] = br1.x;
            Bsn[(lb_k + 17) * (GBN + 4) + lb_j] = br1.y;
            Bsn[(lb_k + 18) * (GBN + 4) + lb_j] = br1.z;
            Bsn[(lb_k + 19) * (GBN + 4) + lb_j] = br1.w;
            Bsn[(lb_k + 32) * (GBN + 4) + lb_j] = br2.x;
            Bsn[(lb_k + 33) * (GBN + 4) + lb_j] = br2.y;
            Bsn[(lb_k + 34) * (GBN + 4) + lb_j] = br2.z;
            Bsn[(lb_k + 35) * (GBN + 4) + lb_j] = br2.w;
            Bsn[(lb_k + 48) * (GBN + 4) + lb_j] = br3.x;
            Bsn[(lb_k + 49) * (GBN + 4) + lb_j] = br3.y;
            Bsn[(lb_k + 50) * (GBN + 4) + lb_j] = br3.z;
            Bsn[(lb_k + 51) * (GBN + 4) + lb_j] = br3.w;
        }
        __syncthreads();
    }

    const int jb = col0 + (tx << 2);
#pragma unroll
    for (int i = 0; i < 3; i++) {
        const int r = row0 + ty * 3 + i;
        float v0, v1, v2, v3;
        f2unpack(acc[i][0], v0, v1);
        f2unpack(acc[i][1], v2, v3);
        if (r < 64) {
            float vv[4] = {v0, v1, v2, v3};
#pragma unroll
            for (int cj = 0; cj < 4; cj++) {
                const int j = jb + cj;
                const int n = j / DC;
                const int d = j - n * DC;
                const int idx = (n * CC + r) * DC + d;
                g_hatm[idx] = vv[cj] + Bb[idx];
            }
        } else {
            float4 o; o.x = v0; o.y = v1; o.z = v2; o.w = v3;
            *(float4*)(g_hq + (size_t)(r - 64) * ND + jb) = o;
        }
    }
}

// =============================================================================
// Kernel B: merged prep + dotq (unchanged).  grid 144.
// =============================================================================
__global__ __launch_bounds__(256, 1)
void prep_dotq_kernel()
{
    extern __shared__ float smP[];
    const int bx = blockIdx.x, t = threadIdx.x;

    if (bx < 128) {
        const int ch = bx & 1, n = (bx >> 1) & 3, qt = bx >> 3;
        float* hq_s = smP;                    // [32][194]
        float* tm_s = smP + 32 * SQ194;       // [32][194]
        float* red  = smP + 64 * SQ194;       // 512

        for (int i = t; i < 32 * 48; i += 256) {
            const int q = i / 48, d4 = (i % 48) << 2;
            float4 v = *(const float4*)&g_hq[(size_t)(qt * 32 + q) * ND + n * DC + d4];
            *(float2*)&hq_s[q * SQ194 + d4]     = make_float2(v.x, v.y);
            *(float2*)&hq_s[q * SQ194 + d4 + 2] = make_float2(v.z, v.w);
        }
        for (int i = t; i < 32 * 48; i += 256) {
            const int c = i / 48, d4 = (i % 48) << 2;
            float4 v = *(const float4*)&g_hatm[(size_t)(n * CC + ch * 32 + c) * DC + d4];
            *(float2*)&tm_s[c * SQ194 + d4]     = make_float2(v.x, v.y);
            *(float2*)&tm_s[c * SQ194 + d4 + 2] = make_float2(v.z, v.w);
        }
        __syncthreads();

        const int qg = t & 15, cg = t >> 4;
        const float* hq0 = hq_s + qg * SQ194;
        const float* hq1 = hq_s + (qg + 16) * SQ194;
        const float* tm0 = tm_s + cg * SQ194;
        const float* tm1 = tm_s + (cg + 16) * SQ194;
        u64 a00 = 0ull, a01 = 0ull, a10 = 0ull, a11 = 0ull;
#pragma unroll 8
        for (int k2 = 0; k2 < 96; k2++) {
            const u64 h0 = *(const u64*)(hq0 + k2 * 2);
            const u64 h1 = *(const u64*)(hq1 + k2 * 2);
            const u64 t0 = *(const u64*)(tm0 + k2 * 2);
            const u64 t1 = *(const u64*)(tm1 + k2 * 2);
            a00 = ffma2(h0, t0, a00);
            a01 = ffma2(h0, t1, a01);
            a10 = ffma2(h1, t0, a10);
            a11 = ffma2(h1, t1, a11);
        }
        const int qb = qt * 32, cb = n * CC + ch * 32;
        float lo, hi;
        f2unpack(a00, lo, hi); g_dq0[(size_t)(qb + qg)      * 256 + cb + cg]      = lo + hi;
        f2unpack(a01, lo, hi); g_dq0[(size_t)(qb + qg)      * 256 + cb + cg + 16] = lo + hi;
        f2unpack(a10, lo, hi); g_dq0[(size_t)(qb + qg + 16) * 256 + cb + cg]      = lo + hi;
        f2unpack(a11, lo, hi); g_dq0[(size_t)(qb + qg + 16) * 256 + cb + cg + 16] = lo + hi;

        if (ch == 0) {
            const int q = t >> 3, seg = t & 7;
            float s = 0.f, sq = 0.f;
            const float* hp = hq_s + q * SQ194 + seg * 24;
#pragma unroll
            for (int k = 0; k < 12; k++) {
                float2 v = *(const float2*)(hp + 2 * k);
                s  += v.x + v.y;
                sq += v.x * v.x + v.y * v.y;
            }
            red[t] = s;
            red[256 + t] = sq;
            __syncthreads();
            if (t < 32) {
                float S = 0.f, SQ = 0.f;
#pragma unroll
                for (int c = 0; c < 8; c++) {
                    S  += red[t * 8 + c];
                    SQ += red[256 + t * 8 + c];
                }
                g_S1[(qt * 32 + t) * NC + n] = S;
                g_ss[(qt * 32 + t) * NC + n] = SQ;
            }
        }
    } else {
        const int idx = bx - 128;
        const int n = idx >> 2, quad = idx & 3;
        float* tm_s = smP;                    // [64][TPAD]

        for (int i = t; i < CC * 48; i += 256) {
            const int r = i / 48, d4 = (i % 48) << 2;
            *(float4*)&tm_s[r * TPAD + d4] =
                *(const float4*)&g_hatm[(size_t)(n * CC + r) * DC + d4];
        }
        __syncthreads();

        if (quad == 0 && t < CC) {
            const float* rp = tm_s + t * TPAD;
            float s = 0.f;
            for (int d = 0; d < DC; d += 4) {
                float4 v = *(const float4*)(rp + d);
                s += (v.x + v.y) + (v.z + v.w);
            }
            const float mu = s * (1.0f / DC);
            float ss = 0.f;
            for (int d = 0; d < DC; d += 4) {
                float4 v = *(const float4*)(rp + d);
                float e0 = v.x - mu, e1 = v.y - mu, e2 = v.z - mu, e3 = v.w - mu;
                ss += (e0 * e0 + e1 * e1) + (e2 * e2 + e3 * e3);
            }
            g_mu[n * CC + t] = mu; g_sxx[n * CC + t] = ss;
        }

        const int c1 = t & 63;
        const int c2b = quad * 16 + ((t >> 6) << 2);
        float acc[4] = {0.f, 0.f, 0.f, 0.f};
        for (int d4 = 0; d4 < DC; d4 += 4) {
            float4 x = *(const float4*)&tm_s[c1 * TPAD + d4];
#pragma unroll
            for (int j = 0; j < 4; j++) {
                float4 y = *(const float4*)&tm_s[(c2b + j) * TPAD + d4];
                acc[j] += (x.x * y.x + x.y * y.y) + (x.z * y.z + x.w * y.w);
            }
        }
        float4 o; o.x = acc[0]; o.y = acc[1]; o.z = acc[2]; o.w = acc[3];
        *(float4*)&g_G[(n * CC + c1) * CC + c2b] = o;
    }
}

// =============================================================================
// Kernel C: MERGED route + out.  grid 128 x 256 thr; CTA owns queries 4bx..4bx+3.
// Phase 1: warps 0-3 route (exact prior code), co_scaled -> smem co_t[n*64+c][4].
// Phase 2: all 8 warps: out[q0+qq][n*192+dp*2] = sum_c co_t[n,c,qq]*tm[n,c,dp*2..]
//          tm streamed from L2 (coalesced LDG.64, unroll-8 MLP).
// Smem: G_s 17408 fl + co_t 1024 fl = 73728 B.
// =============================================================================
__global__ __launch_bounds__(256, 1)
void route_out_kernel(float* __restrict__ out)
{
    extern __shared__ float smD[];
    float* G_s  = smD;                      // [4*64][GPAD]
    float* co_t = smD + NC * CC * GPAD;     // [256][4]  (c-major, q minor)

    const int t = threadIdx.x, lane = t & 31, w = t >> 5;
    const int q0 = blockIdx.x * 4;

    for (int i = t; i < NC * CC * 16; i += 256) {
        const int row = i >> 4, c4 = (i & 15) << 2;
        *(float4*)&G_s[row * GPAD + c4] = *(const float4*)&g_G[row * CC + c4];
    }
    __syncthreads();

    // ---- Phase 1: routing (warps 0-3; one query each) ----
    if (w < 4) {
        const int q = q0 + w;
        // co working buffer per warp lives in G_s? No - use registers + smem co row
        // scratch: reuse co_t row-major temporarily is unsafe (other warps write too).
        // Each warp needs a 256-float scratch for its co vector during GEMV:
        // store it transposed directly into co_t ([c][4q]) and read strided.
        float mu[NC][2], sxx[NC][2], dq[NC][2], a[NC][2], p[NC][2], co[NC][2];
        float S1[NC], ss[NC];
#pragma unroll
        for (int n = 0; n < NC; n++) {
#pragma unroll
            for (int j = 0; j < 2; j++) {
                const int idx = n * CC + lane + 32 * j;
                mu[n][j]  = g_mu[idx];
                sxx[n][j] = g_sxx[idx];
                dq[n][j]  = g_dq0[(size_t)q * 256 + idx];
                a[n][j]   = 0.f;
            }
            S1[n] = g_S1[q * NC + n];
            ss[n] = g_ss[q * NC + n];
            const float syy = ss[n] - S1[n] * S1[n] * (1.0f / DC);
#pragma unroll
            for (int j = 0; j < 2; j++)
                p[n][j] = tanhf(-(dq[n][j] - mu[n][j] * S1[n])
                                * rsqrtf(sxx[n][j] * syy + EPSF));
        }

#pragma unroll 1
        for (int it = 0; it < 3; it++) {
#pragma unroll
            for (int j = 0; j < 2; j++) {
                float mx = fmaxf(fmaxf(a[0][j], a[1][j]), fmaxf(a[2][j], a[3][j]));
                float e0 = expf(a[0][j] - mx), e1 = expf(a[1][j] - mx);
                float e2 = expf(a[2][j] - mx), e3 = expf(a[3][j] - mx);
                float inv = 1.0f / (e0 + e1 + e2 + e3);
                co[0][j] = e0 * inv + p[0][j];
                co[1][j] = e1 * inv + p[1][j];
                co[2][j] = e2 * inv + p[2][j];
                co[3][j] = e3 * inv + p[3][j];
            }
            // publish co into co_t[(n*64+c)][w]
#pragma unroll
            for (int n = 0; n < NC; n++) {
                co_t[(n * CC + lane) * 4 + w]        = co[n][0];
                co_t[(n * CC + lane + 32) * 4 + w]   = co[n][1];
            }
            __syncwarp();

            float gc[NC][2];
#pragma unroll
            for (int n = 0; n < NC; n++) {
                const float* r0 = &G_s[(n * CC + lane) * GPAD];
                const float* r1 = &G_s[(n * CC + lane + 32) * GPAD];
                const float* cw = co_t + n * CC * 4 + w;
                float a0 = 0.f, a1 = 0.f;
#pragma unroll
                for (int c = 0; c < CC; c += 4) {
                    float4 g0 = *(const float4*)(r0 + c);
                    float4 g1 = *(const float4*)(r1 + c);
                    const float c0 = cw[(c + 0) * 4];
                    const float c1 = cw[(c + 1) * 4];
                    const float c2 = cw[(c + 2) * 4];
                    const float c3 = cw[(c + 3) * 4];
                    a0 += (c0 * g0.x + c1 * g0.y) + (c2 * g0.z + c3 * g0.w);
                    a1 += (c0 * g1.x + c1 * g1.y) + (c2 * g1.z + c3 * g1.w);
                }
                gc[n][0] = a0; gc[n][1] = a1;
            }

            float rS[NC], rD[NC], rM[NC];
#pragma unroll
            for (int n = 0; n < NC; n++) {
                rS[n] = co[n][0] * gc[n][0] + co[n][1] * gc[n][1];
                rD[n] = co[n][0] * dq[n][0] + co[n][1] * dq[n][1];
                rM[n] = co[n][0] * mu[n][0] + co[n][1] * mu[n][1];
            }
#pragma unroll
            for (int o = 16; o > 0; o >>= 1)
#pragma unroll
                for (int n = 0; n < NC; n++) {
                    rS[n] += __shfl_xor_sync(0xffffffffu, rS[n], o);
                    rD[n] += __shfl_xor_sync(0xffffffffu, rD[n], o);
                    rM[n] += __shfl_xor_sync(0xffffffffu, rM[n], o);
                }

            if (it == 2) {
                // final: scaled co into co_t (q minor)
#pragma unroll
                for (int n = 0; n < NC; n++) {
                    const float s = rS[n];
                    const float scale = s / ((1.0f + s) * sqrtf(s + EPSF));
                    co_t[(n * CC + lane) * 4 + w]      = co[n][0] * scale;
                    co_t[(n * CC + lane + 32) * 4 + w] = co[n][1] * scale;
                }
                break;
            }

#pragma unroll
            for (int n = 0; n < NC; n++) {
                const float s = rS[n];
                const float scale = s / ((1.0f + s) * sqrtf(s + EPSF));
                const float S1n = 0.5f * (S1[n] + scale * (float)DC * rM[n]);
                const float ssn = 0.25f * (ss[n] + 2.0f * scale * rD[n]
                                           + scale * scale * s);
#pragma unroll
                for (int j = 0; j < 2; j++) {
                    const float ag = scale * gc[n][j];
                    a[n][j] += p[n][j] * ag;
                    dq[n][j] = 0.5f * (dq[n][j] + ag);
                }
                S1[n] = S1n; ss[n] = ssn;
                const float syy = ssn - S1n * S1n * (1.0f / DC);
#pragma unroll
                for (int j = 0; j < 2; j++)
                    p[n][j] = tanhf(-(dq[n][j] - mu[n][j] * S1n)
                                    * rsqrtf(sxx[n][j] * syy + EPSF));
            }
            __syncwarp();
        }
    }
    __syncthreads();

    // ---- Phase 2: out[4q][768]; slot = (n, d-pair), all 8 warps ----
#pragma unroll
    for (int rep = 0; rep < 2; rep++) {
        const int s = t + rep * 256;
        if (s < NC * 96) {
            const int n  = s / 96;
            const int dp = s - n * 96;
            const float* tmb = g_hatm + (size_t)(n * CC) * DC + dp * 2;
            const float* cob = co_t + n * CC * 4;
            u64 a0 = 0ull, a1 = 0ull, a2 = 0ull, a3 = 0ull;
#pragma unroll 8
            for (int c = 0; c < CC; c++) {
                const u64 tv = *(const u64*)(tmb + (size_t)c * DC);
                float4 cv = *(const float4*)(cob + c * 4);
                a0 = ffma2(f2dup(cv.x), tv, a0);
                a1 = ffma2(f2dup(cv.y), tv, a1);
                a2 = ffma2(f2dup(cv.z), tv, a2);
                a3 = ffma2(f2dup(cv.w), tv, a3);
            }
            float lo, hi;
            float* ob = out + (size_t)q0 * ND + n * DC + dp * 2;
            f2unpack(a0, lo, hi); *(float2*)(ob)          = make_float2(lo, hi);
            f2unpack(a1, lo, hi); *(float2*)(ob + ND)     = make_float2(lo, hi);
            f2unpack(a2, lo, hi); *(float2*)(ob + 2 * ND) = make_float2(lo, hi);
            f2unpack(a3, lo, hi); *(float2*)(ob + 3 * ND) = make_float2(lo, hi);
        }
    }
}

// =============================================================================
// launch
// =============================================================================
extern "C" void kernel_launch(void* const* d_in, const int* in_sizes, int n_in,
                              void* d_out, int out_size)
{
    const float* m = (const float*)d_in[0];
    const float* q = (const float*)d_in[1];
    const float* W = (const float*)d_in[2];
    const float* b = (const float*)d_in[3];
    float* out = (float*)d_out;
    (void)in_sizes; (void)n_in; (void)out_size;

    const int smG = 2 * TILEBUF * 4;                        // 60928
    const int smP = (64 * SQ194 + 512) * 4;                 // 51712
    const int smD = (NC * CC * GPAD + NC * CC * 4) * 4;     // 73728
    cudaFuncSetAttribute(gemm_kernel, cudaFuncAttributeMaxDynamicSharedMemorySize, smG);
    cudaFuncSetAttribute(prep_dotq_kernel, cudaFuncAttributeMaxDynamicSharedMemorySize, smP);
    cudaFuncSetAttribute(route_out_kernel, cudaFuncAttributeMaxDynamicSharedMemorySize, smD);

    gemm_kernel<<<dim3(12, 12), 256, smG>>>(m, q, W, b);
    prep_dotq_kernel<<<144, 256, smP>>>();
    route_out_kernel<<<128, 256, smD>>>(out);
}